// round 1
// baseline (speedup 1.0000x reference)
#include <cuda_runtime.h>
#include <math.h>

#define BB 16
#define AA 3
#define SS_DIM 80
#define NC 80
#define NT 32
#define SS (SS_DIM * SS_DIM)          // 6400
#define CH (5 + NC)                   // 85
#define CELLS (BB * AA * SS)          // 307200
#define EPSF 1e-7f
#define IMG 640.0f
#define STRIDEF 8.0f

// scratch (no allocations allowed)
__device__ int    g_obj[CELLS];
__device__ int    g_nobj;
// 0: sum softplus(conf) all cells, 1: sum ciou (obj), 2: sum bce(conf,1) (obj),
// 3: sum softplus(conf) at obj cells (correction), 4: sum cls bce (obj)
__device__ double g_acc[5];

__device__ __forceinline__ float softplusf(float x) {
    return fmaxf(x, 0.0f) + log1pf(expf(-fabsf(x)));
}
__device__ __forceinline__ float sigmoidf(float x) {
    return 1.0f / (1.0f + expf(-x));
}

// ---------------------------------------------------------------------------
__global__ void k_zero() {
    int i = blockIdx.x * blockDim.x + threadIdx.x;
    if (i < CELLS) g_obj[i] = 0;
    if (i == 0) {
        g_nobj = 0;
        for (int j = 0; j < 5; j++) g_acc[j] = 0.0;
    }
}

// ---------------------------------------------------------------------------
// Sum of softplus(conf) over ALL cells (coalesced: consecutive i -> consecutive
// spatial index within one (b, a) channel plane).
__global__ void k_conf_sum(const float* __restrict__ preds) {
    int i = blockIdx.x * blockDim.x + threadIdx.x;
    float v = 0.0f;
    if (i < CELLS) {
        int ba = i / SS;            // b * AA + a
        int sp = i - ba * SS;
        int b = ba / AA;
        int a = ba - b * AA;
        size_t off = ((size_t)b * (AA * CH) + (size_t)a * CH + 4) * SS + sp;
        v = softplusf(preds[off]);
    }
    // warp reduce
    for (int o = 16; o > 0; o >>= 1)
        v += __shfl_down_sync(0xffffffffu, v, o);
    __shared__ float warp_sums[8];
    int lane = threadIdx.x & 31, wid = threadIdx.x >> 5;
    if (lane == 0) warp_sums[wid] = v;
    __syncthreads();
    if (wid == 0) {
        v = (lane < (blockDim.x >> 5)) ? warp_sums[lane] : 0.0f;
        for (int o = 4; o > 0; o >>= 1)
            v += __shfl_down_sync(0xffffffffu, v, o);
        if (lane == 0) atomicAdd(&g_acc[0], (double)v);
    }
}

// ---------------------------------------------------------------------------
__device__ __forceinline__ void assign_target(
    const float* __restrict__ tbox, const float* aw, const float* ah,
    int b, int m, int& a, int& gi, int& gj)
{
    const float* p = tbox + (size_t)(b * NT + m) * 4;
    float x = p[0], y = p[1], w = p[2], h = p[3];
    gi = min(max((int)floorf(x * (float)SS_DIM), 0), SS_DIM - 1);
    gj = min(max((int)floorf(y * (float)SS_DIM), 0), SS_DIM - 1);
    float tw = w * IMG, th = h * IMG;
    float best = -1.0f; a = 0;
    #pragma unroll
    for (int k = 0; k < AA; k++) {
        float inter = fminf(tw, aw[k]) * fminf(th, ah[k]);
        float un = tw * th + aw[k] * ah[k] - inter;
        float r = inter / un;
        if (r > best) { best = r; a = k; }   // first max wins (jnp.argmax)
    }
}

__device__ __forceinline__ float ciou_f(
    float px1, float py1, float px2, float py2,
    float tx1, float ty1, float tx2, float ty2)
{
    float iw = fmaxf(fminf(px2, tx2) - fmaxf(px1, tx1), 0.0f);
    float ih = fmaxf(fminf(py2, ty2) - fmaxf(py1, ty1), 0.0f);
    float inter = iw * ih;
    float pa = fmaxf(px2 - px1, 0.0f) * fmaxf(py2 - py1, 0.0f);
    float ta = fmaxf(tx2 - tx1, 0.0f) * fmaxf(ty2 - ty1, 0.0f);
    float un = pa + ta - inter + EPSF;
    float iou = inter / un;
    float dx = 0.5f * (px1 + px2) - 0.5f * (tx1 + tx2);
    float dy = 0.5f * (py1 + py2) - 0.5f * (ty1 + ty2);
    float cd = dx * dx + dy * dy;
    float ew = fmaxf(px2, tx2) - fminf(px1, tx1);
    float eh = fmaxf(py2, ty2) - fminf(py1, ty1);
    float ed = ew * ew + eh * eh + EPSF;
    float pw = fmaxf(px2 - px1, EPSF);
    float ph = fmaxf(py2 - py1, EPSF);
    float tw = fmaxf(tx2 - tx1, EPSF);
    float th = fmaxf(ty2 - ty1, EPSF);
    float da = atanf(tw / th) - atanf(pw / ph);
    float v = (4.0f / ((float)M_PI * (float)M_PI)) * da * da;
    float alpha = v / (1.0f - iou + v + EPSF);
    return iou - cd / ed - alpha * v;
}

// One thread per target. Owner (first to flip obj flag) does all per-cell work.
__global__ void k_targets(const float* __restrict__ preds,
                          const float* __restrict__ anchors,
                          const int* __restrict__ tcls,
                          const float* __restrict__ tbox)
{
    int t = threadIdx.x;
    if (t >= BB * NT) return;
    float aw[AA], ah[AA];
    #pragma unroll
    for (int k = 0; k < AA; k++) { aw[k] = anchors[2 * k]; ah[k] = anchors[2 * k + 1]; }

    int b = t / NT, n = t - b * NT;
    int a, gi, gj;
    assign_target(tbox, aw, ah, b, n, a, gi, gj);
    int cell = ((b * AA + a) * SS_DIM + gj) * SS_DIM + gi;

    int old = atomicExch(&g_obj[cell], 1);
    if (old != 0) return;   // another thread owns this cell

    // Owner: rescan all targets in this batch mapping to this cell.
    // Class set may contain multiple classes; box is last-wins (largest m).
    unsigned clsbits[3] = {0u, 0u, 0u};
    float wx1 = 0.f, wy1 = 0.f, wx2 = 0.f, wy2 = 0.f;
    for (int m = 0; m < NT; m++) {
        int am, gim, gjm;
        assign_target(tbox, aw, ah, b, m, am, gim, gjm);
        if (am == a && gim == gi && gjm == gj) {
            int c = tcls[b * NT + m];
            clsbits[c >> 5] |= (1u << (c & 31));
            const float* p = tbox + (size_t)(b * NT + m) * 4;
            float cx = p[0] * IMG, cy = p[1] * IMG;
            float tw = p[2] * IMG, th = p[3] * IMG;
            wx1 = cx - 0.5f * tw; wy1 = cy - 0.5f * th;
            wx2 = cx + 0.5f * tw; wy2 = cy + 0.5f * th;
        }
    }

    // Predictions at this cell (channel stride = SS floats)
    size_t base = ((size_t)b * (AA * CH) + (size_t)a * CH) * SS
                  + (size_t)gj * SS_DIM + gi;
    float p0 = preds[base];
    float p1 = preds[base + (size_t)SS];
    float p2 = preds[base + (size_t)2 * SS];
    float p3 = preds[base + (size_t)3 * SS];
    float pc = preds[base + (size_t)4 * SS];

    float pcx = (sigmoidf(p0) + (float)gi) * STRIDEF;
    float pcy = (sigmoidf(p1) + (float)gj) * STRIDEF;
    float pw = aw[a] * expf(p2);
    float ph = ah[a] * expf(p3);
    float px1 = pcx - 0.5f * pw, py1 = pcy - 0.5f * ph;
    float px2 = pcx + 0.5f * pw, py2 = pcy + 0.5f * ph;

    float ciou = ciou_f(px1, py1, px2, py2, wx1, wy1, wx2, wy2);

    float sp_c = softplusf(pc);
    float bce_obj = sp_c - pc;          // bce(conf, 1)

    float cls_sum = 0.0f;
    #pragma unroll 4
    for (int c = 0; c < NC; c++) {
        float l = preds[base + (size_t)(5 + c) * SS];
        float tgt = (float)((clsbits[c >> 5] >> (c & 31)) & 1u);
        cls_sum += softplusf(l) - l * tgt;
    }

    atomicAdd(&g_nobj, 1);
    atomicAdd(&g_acc[1], (double)ciou);
    atomicAdd(&g_acc[2], (double)bce_obj);
    atomicAdd(&g_acc[3], (double)sp_c);     // subtract from all-cells softplus sum
    atomicAdd(&g_acc[4], (double)cls_sum);
}

// ---------------------------------------------------------------------------
__global__ void k_final(float* __restrict__ out) {
    double nobj = (double)g_nobj;
    double dn_obj = fmax(nobj, 1.0);
    double dn_noobj = fmax((double)CELLS - nobj, 1.0);
    double dn_cls = fmax(nobj * (double)NC, 1.0);

    double loss_ciou = 1.0 - g_acc[1] / dn_obj;
    double loss_conf_obj = g_acc[2] / dn_obj;
    double loss_conf_noobj = (g_acc[0] - g_acc[3]) / dn_noobj;
    double loss_cls = g_acc[4] / dn_cls;

    out[0] = (float)(loss_ciou + loss_conf_obj + 0.5 * loss_conf_noobj + loss_cls);
}

// ---------------------------------------------------------------------------
extern "C" void kernel_launch(void* const* d_in, const int* in_sizes, int n_in,
                              void* d_out, int out_size)
{
    const float* preds   = (const float*)d_in[0];
    const float* anchors = (const float*)d_in[1];
    const int*   tcls    = (const int*)d_in[2];
    const float* tbox    = (const float*)d_in[3];
    float* out = (float*)d_out;

    k_zero<<<(CELLS + 255) / 256, 256>>>();
    k_conf_sum<<<(CELLS + 255) / 256, 256>>>(preds);
    k_targets<<<1, 512>>>(preds, anchors, tcls, tbox);
    k_final<<<1, 1>>>(out);
}